// round 8
// baseline (speedup 1.0000x reference)
#include <cuda_runtime.h>
#include <math.h>

// Problem constants (fixed by the reference)
#define NN      64
#define GRID_N  (NN * NN * NN)   // 262144
#define NQ      200
#define BATCH   2
#define CH      8                // threads cooperating per boundary point
#define QPT     (NQ / CH)        // 25 charges per thread
#define TPB     256
#define PPB     (TPB / CH)       // 32 boundary points per block
#define MAXB    1024

// Scratch for cross-block reduction (allocation-free __device__ global).
// Every live slot is overwritten every launch -> deterministic across replays.
__device__ float g_partials[MAXB];

__global__ __launch_bounds__(TPB)
void ibl_loss_kernel(const float* __restrict__ field,    // (BATCH,1,64,64,64)
                     const float* __restrict__ q,        // (NQ,)
                     const float* __restrict__ xq,       // (NQ,3)
                     const int*   __restrict__ xi,
                     const int*   __restrict__ yi,
                     const int*   __restrict__ zi,
                     const float* __restrict__ normals,  // (NB,3)
                     int nb)
{
    __shared__ float4 sq[NQ];   // {xq.x, xq.y, xq.z, q}

    const float  EPSF   = 1.1920929e-07f;               // np.finfo(float32).eps
    const float  INV4PI = 1.0f / (4.0f * 3.14159265358979323846f);
    const double DXD    = 1.0 / 63.0;                   // reference DX (float64)
    const float  RDX    = 63.0f;                        // 1/DX in fp32

    const int tid  = threadIdx.x;
    const int gtid = blockIdx.x * TPB + tid;
    const int i    = gtid >> 3;        // boundary point index
    const int c    = gtid & (CH - 1);  // charge-chunk index within point
    const bool leader = (c == 0) && (i < nb);

    // ---- Issue index loads immediately
    int x = 0, y = 0, z = 0;
    if (i < nb) { x = xi[i]; y = yi[i]; z = zi[i]; }

    // ---- Stage charges into shared (one per thread, 200 <= 256)
    if (tid < NQ) {
        sq[tid] = make_float4(xq[3 * tid + 0], xq[3 * tid + 1],
                              xq[3 * tid + 2], q[tid]);
    }

    const int flat = (x * NN + y) * NN + z;

    // ---- Hoisted leader loads: normals + field stencil (both batches)
    float nx = 0.f, ny = 0.f, nz = 0.f;
    float c0[BATCH], lft[BATCH], rgt[BATCH], bel[BATCH], abv[BATCH], bck[BATCH], frt[BATCH];
    if (leader) {
        nx = normals[3 * i + 0];
        ny = normals[3 * i + 1];
        nz = normals[3 * i + 2];
        #pragma unroll
        for (int b = 0; b < BATCH; b++) {
            const float* __restrict__ o = field + b * GRID_N;
            c0[b]  = o[flat];
            lft[b] = o[flat - NN * NN];
            rgt[b] = o[flat + NN * NN];
            bel[b] = o[flat - NN];
            abv[b] = o[flat + NN];
            bck[b] = o[flat - 1];
            frt[b] = o[flat + 1];
        }
    } else {
        #pragma unroll
        for (int b = 0; b < BATCH; b++) {
            c0[b] = lft[b] = rgt[b] = bel[b] = abv[b] = bck[b] = frt[b] = 0.f;
        }
    }

    // ---- Grid-point coords: bit-exact replica of reference's fp64->fp32 points
    const float px = (float)((double)x * DXD);
    const float py = (float)((double)y * DXD);
    const float pz = (float)((double)z * DXD);

    __syncthreads();   // sq ready

    // ---- Green's function partial sums over this thread's 25 charges
    float g = 0.0f, gx = 0.0f, gy = 0.0f, gz = 0.0f;
    if (i < nb) {
        const int k0 = c * QPT;
        #pragma unroll
        for (int kk = 0; kk < QPT; kk++) {
            const float4 ch = sq[k0 + kk];
            const float dx = px - ch.x;
            const float dy = py - ch.y;
            const float dz = pz - ch.z;
            const float r2 = fmaf(dx, dx, fmaf(dy, dy, dz * dz));
            const float inv_r  = (r2 > 0.0f) ? rsqrtf(r2) : (1.0f / EPSF);
            g = fmaf(ch.w, inv_r, g);
            const float inv_r3 = inv_r * inv_r * inv_r;
            const float coef   = -ch.w * inv_r3;
            gx = fmaf(coef, dx, gx);
            gy = fmaf(coef, dy, gy);
            gz = fmaf(coef, dz, gz);
        }
    }

    // ---- Reduce 4 accumulators across the 8-thread group
    #pragma unroll
    for (int off = CH / 2; off > 0; off >>= 1) {
        g  += __shfl_down_sync(0xffffffffu, g,  off, CH);
        gx += __shfl_down_sync(0xffffffffu, gx, off, CH);
        gy += __shfl_down_sync(0xffffffffu, gy, off, CH);
        gz += __shfl_down_sync(0xffffffffu, gz, off, CH);
    }

    float local = 0.0f;
    if (leader) {
        g  *= INV4PI;
        gx *= INV4PI;
        gy *= INV4PI;
        gz *= INV4PI;

        const float gcnd = gx * nx + gy * ny + gz * nz;

        // loss1: (mol_b - out_b)^2 == g^2, identical for both batches
        local = (float)BATCH * (g * g);

        // loss2: one-sided normal derivatives per batch (preloaded stencil)
        #pragma unroll
        for (int b = 0; b < BATCH; b++) {
            const float dmx = (c0[b]  - lft[b]) * RDX;
            const float dpx = (rgt[b] - c0[b])  * RDX;
            const float dmy = (c0[b]  - bel[b]) * RDX;
            const float dpy = (abv[b] - c0[b])  * RDX;
            const float dmz = (c0[b]  - bck[b]) * RDX;
            const float dpz = (frt[b] - c0[b])  * RDX;

            const float gx_in  = (nx > 0.0f) ? dmx : dpx;
            const float gx_out = (nx > 0.0f) ? dpx : dmx;
            const float gy_in  = (ny > 0.0f) ? dmy : dpy;
            const float gy_out = (ny > 0.0f) ? dpy : dmy;
            const float gz_in  = (nz > 0.0f) ? dmz : dpz;
            const float gz_out = (nz > 0.0f) ? dpz : dmz;

            const float nd_in  = gx_in  * nx + gy_in  * ny + gz_in  * nz;
            const float nd_out = gx_out * nx + gy_out * ny + gz_out * nz;

            // E_IN = 1, E_OUT = 80
            const float t = (nd_in + gcnd) - 80.0f * nd_out;
            local = fmaf(t, t, local);
        }
    }

    // ---- Block reduction; then ONE plain store per block. No atomics, no fence.
    float v = local;
    #pragma unroll
    for (int off = 16; off > 0; off >>= 1)
        v += __shfl_down_sync(0xffffffffu, v, off);

    __shared__ float wsum[TPB / 32];
    const int warp = tid >> 5;
    const int lane = tid & 31;
    if (lane == 0) wsum[warp] = v;
    __syncthreads();

    if (warp == 0) {
        v = (lane < (TPB / 32)) ? wsum[lane] : 0.0f;
        #pragma unroll
        for (int off = (TPB / 64); off > 0; off >>= 1)
            v += __shfl_down_sync(0xffffffffu, v, off);
        if (lane == 0)
            g_partials[blockIdx.x] = v;   // plain STG; graph edge orders it
    }
}

// Finisher: one warp reduces the partials, scales, writes the scalar loss.
__global__ __launch_bounds__(32)
void ibl_finish_kernel(int nblocks, int nb, float* __restrict__ out)
{
    const int lane = threadIdx.x;
    float s = 0.0f;
    for (int j = lane; j < nblocks; j += 32)
        s += g_partials[j];
    #pragma unroll
    for (int off = 16; off > 0; off >>= 1)
        s += __shfl_down_sync(0xffffffffu, s, off);
    if (lane == 0)
        out[0] = s * (1.0f / (float)(BATCH * nb));
}

extern "C" void kernel_launch(void* const* d_in, const int* in_sizes, int n_in,
                              void* d_out, int out_size)
{
    const float* field   = (const float*)d_in[0];  // output (2,1,64,64,64)
    const float* q       = (const float*)d_in[1];  // (200,)
    const float* xq      = (const float*)d_in[2];  // (200,3)
    // d_in[3] = points (recomputed on device bit-exactly)
    const int*   xi      = (const int*)  d_in[4];
    const int*   yi      = (const int*)  d_in[5];
    const int*   zi      = (const int*)  d_in[6];
    const float* normals = (const float*)d_in[7];  // (NB,3)
    float*       out     = (float*)d_out;

    const int nb = in_sizes[4];

    int blocks = (nb + PPB - 1) / PPB;   // ~147 for nb ~ 4.7K
    if (blocks > MAXB) blocks = MAXB;

    ibl_loss_kernel<<<blocks, TPB>>>(field, q, xq, xi, yi, zi, normals, nb);
    ibl_finish_kernel<<<1, 32>>>(blocks, nb, out);
}

// round 10
// speedup vs baseline: 1.1922x; 1.1922x over previous
#include <cuda_runtime.h>
#include <math.h>

// Problem constants (fixed by the reference)
#define NN      64
#define GRID_N  (NN * NN * NN)   // 262144
#define NQ      200
#define BATCH   2
#define CH      8                // threads cooperating per boundary point
#define QPT     (NQ / CH)        // 25 charges per thread
#define TPB     256
#define PPB     (TPB / CH)       // 32 boundary points per block

// Cross-block reduction state (allocation-free __device__ globals).
// g_accum is reset to 0 by the last block each launch -> replay-safe.
__device__ float        g_accum  = 0.0f;
__device__ unsigned int g_ticket = 0;     // self-resetting via atomicInc wrap

__global__ __launch_bounds__(TPB)
void ibl_loss_kernel(const float* __restrict__ field,    // (BATCH,1,64,64,64)
                     const float* __restrict__ q,        // (NQ,)
                     const float* __restrict__ xq,       // (NQ,3)
                     const int*   __restrict__ xi,
                     const int*   __restrict__ yi,
                     const int*   __restrict__ zi,
                     const float* __restrict__ normals,  // (NB,3)
                     int nb,
                     float* __restrict__ out)
{
    __shared__ float4 sq[NQ];   // {xq.x, xq.y, xq.z, q}

    const float  EPSF   = 1.1920929e-07f;               // np.finfo(float32).eps
    const float  INV4PI = 1.0f / (4.0f * 3.14159265358979323846f);
    const double DXD    = 1.0 / 63.0;                   // reference DX (float64)
    const float  RDX    = 63.0f;                        // 1/DX in fp32

    const int tid  = threadIdx.x;
    const int gtid = blockIdx.x * TPB + tid;
    const int i    = gtid >> 3;        // boundary point index
    const int c    = gtid & (CH - 1);  // charge-chunk index within point
    const bool leader = (c == 0) && (i < nb);

    // ---- Issue index loads immediately (start the memory round-trip early)
    int x = 0, y = 0, z = 0;
    if (i < nb) { x = xi[i]; y = yi[i]; z = zi[i]; }

    // ---- Stage charges into shared (one per thread, 200 <= 256)
    if (tid < NQ) {
        sq[tid] = make_float4(xq[3 * tid + 0], xq[3 * tid + 1],
                              xq[3 * tid + 2], q[tid]);
    }

    const int flat = (x * NN + y) * NN + z;

    // ---- Hoisted leader loads: normals + field stencil (both batches);
    //      their latency overlaps staging + the charge loop.
    float nx = 0.f, ny = 0.f, nz = 0.f;
    float c0[BATCH], lft[BATCH], rgt[BATCH], bel[BATCH], abv[BATCH], bck[BATCH], frt[BATCH];
    if (leader) {
        nx = normals[3 * i + 0];
        ny = normals[3 * i + 1];
        nz = normals[3 * i + 2];
        #pragma unroll
        for (int b = 0; b < BATCH; b++) {
            const float* __restrict__ o = field + b * GRID_N;
            c0[b]  = o[flat];
            lft[b] = o[flat - NN * NN];
            rgt[b] = o[flat + NN * NN];
            bel[b] = o[flat - NN];
            abv[b] = o[flat + NN];
            bck[b] = o[flat - 1];
            frt[b] = o[flat + 1];
        }
    } else {
        #pragma unroll
        for (int b = 0; b < BATCH; b++) {
            c0[b] = lft[b] = rgt[b] = bel[b] = abv[b] = bck[b] = frt[b] = 0.f;
        }
    }

    // ---- Grid-point coords: bit-exact replica of reference's fp64->fp32 points
    const float px = (float)((double)x * DXD);
    const float py = (float)((double)y * DXD);
    const float pz = (float)((double)z * DXD);

    __syncthreads();   // sq ready

    // ---- Green's function partial sums over this thread's 25 charges
    float g = 0.0f, gx = 0.0f, gy = 0.0f, gz = 0.0f;
    if (i < nb) {
        const int k0 = c * QPT;
        #pragma unroll
        for (int kk = 0; kk < QPT; kk++) {
            const float4 ch = sq[k0 + kk];
            const float dx = px - ch.x;
            const float dy = py - ch.y;
            const float dz = pz - ch.z;
            const float r2 = fmaf(dx, dx, fmaf(dy, dy, dz * dz));
            const float inv_r  = (r2 > 0.0f) ? rsqrtf(r2) : (1.0f / EPSF);
            g = fmaf(ch.w, inv_r, g);
            const float inv_r3 = inv_r * inv_r * inv_r;
            const float coef   = -ch.w * inv_r3;
            gx = fmaf(coef, dx, gx);
            gy = fmaf(coef, dy, gy);
            gz = fmaf(coef, dz, gz);
        }
    }

    // ---- Reduce 4 accumulators across the 8-thread group
    #pragma unroll
    for (int off = CH / 2; off > 0; off >>= 1) {
        g  += __shfl_down_sync(0xffffffffu, g,  off, CH);
        gx += __shfl_down_sync(0xffffffffu, gx, off, CH);
        gy += __shfl_down_sync(0xffffffffu, gy, off, CH);
        gz += __shfl_down_sync(0xffffffffu, gz, off, CH);
    }

    float local = 0.0f;
    if (leader) {
        g  *= INV4PI;
        gx *= INV4PI;
        gy *= INV4PI;
        gz *= INV4PI;

        const float gcnd = gx * nx + gy * ny + gz * nz;

        // loss1: (mol_b - out_b)^2 == g^2, identical for both batches
        local = (float)BATCH * (g * g);

        // loss2: one-sided normal derivatives per batch (preloaded stencil)
        #pragma unroll
        for (int b = 0; b < BATCH; b++) {
            const float dmx = (c0[b]  - lft[b]) * RDX;
            const float dpx = (rgt[b] - c0[b])  * RDX;
            const float dmy = (c0[b]  - bel[b]) * RDX;
            const float dpy = (abv[b] - c0[b])  * RDX;
            const float dmz = (c0[b]  - bck[b]) * RDX;
            const float dpz = (frt[b] - c0[b])  * RDX;

            const float gx_in  = (nx > 0.0f) ? dmx : dpx;
            const float gx_out = (nx > 0.0f) ? dpx : dmx;
            const float gy_in  = (ny > 0.0f) ? dmy : dpy;
            const float gy_out = (ny > 0.0f) ? dpy : dmy;
            const float gz_in  = (nz > 0.0f) ? dmz : dpz;
            const float gz_out = (nz > 0.0f) ? dpz : dmz;

            const float nd_in  = gx_in  * nx + gy_in  * ny + gz_in  * nz;
            const float nd_out = gx_out * nx + gy_out * ny + gz_out * nz;

            // E_IN = 1, E_OUT = 80
            const float t = (nd_in + gcnd) - 80.0f * nd_out;
            local = fmaf(t, t, local);
        }
    }

    // ---- Block reduction
    float v = local;
    #pragma unroll
    for (int off = 16; off > 0; off >>= 1)
        v += __shfl_down_sync(0xffffffffu, v, off);

    __shared__ float wsum[TPB / 32];
    const int warp = tid >> 5;
    const int lane = tid & 31;
    if (lane == 0) wsum[warp] = v;
    __syncthreads();

    if (warp == 0) {
        v = (lane < (TPB / 32)) ? wsum[lane] : 0.0f;
        #pragma unroll
        for (int off = (TPB / 64); off > 0; off >>= 1)
            v += __shfl_down_sync(0xffffffffu, v, off);
    }

    // ---- Cross-block tail: ONE atomicAdd + ONE ticket per block.
    //      Last block reads a single word, scales, writes out, resets.
    const int nblocks = gridDim.x;
    __shared__ bool s_is_last;
    if (tid == 0) {
        atomicAdd(&g_accum, v);
        __threadfence();
        unsigned int t = atomicInc(&g_ticket, (unsigned int)(nblocks - 1));
        s_is_last = (t == (unsigned int)(nblocks - 1));
    }
    __syncthreads();

    if (s_is_last && tid == 0) {
        __threadfence();                       // acquire: see all g_accum adds
        volatile float* ap = &g_accum;
        const float s = *ap;
        out[0] = s * (1.0f / (float)(BATCH * nb));
        *ap = 0.0f;                            // reset for next graph replay
        __threadfence();
    }
}

extern "C" void kernel_launch(void* const* d_in, const int* in_sizes, int n_in,
                              void* d_out, int out_size)
{
    const float* field   = (const float*)d_in[0];  // output (2,1,64,64,64)
    const float* q       = (const float*)d_in[1];  // (200,)
    const float* xq      = (const float*)d_in[2];  // (200,3)
    // d_in[3] = points (recomputed on device bit-exactly)
    const int*   xi      = (const int*)  d_in[4];
    const int*   yi      = (const int*)  d_in[5];
    const int*   zi      = (const int*)  d_in[6];
    const float* normals = (const float*)d_in[7];  // (NB,3)
    float*       out     = (float*)d_out;

    const int nb = in_sizes[4];

    const int blocks = (nb + PPB - 1) / PPB;   // ~147 for nb ~ 4.7K

    ibl_loss_kernel<<<blocks, TPB>>>(field, q, xq, xi, yi, zi, normals, nb, out);
}

// round 13
// speedup vs baseline: 1.1964x; 1.0036x over previous
#include <cuda_runtime.h>
#include <math.h>

// Problem constants (fixed by the reference)
#define NN      64
#define GRID_N  (NN * NN * NN)   // 262144
#define NQ      200
#define BATCH   2
#define CH      8                // threads cooperating per boundary point
#define QPT     (NQ / CH)        // 25 charges per thread
#define TPB     256
#define PPB     (TPB / CH)       // 32 boundary points per block
#define MAXB    2048

// Cross-block state (allocation-free __device__ globals).
// g_count is reset by block 0 at the end of every launch -> replay-safe.
__device__ float                 g_partials[MAXB];
__device__ volatile unsigned int g_count = 0;

__global__ __launch_bounds__(TPB)
void ibl_loss_kernel(const float* __restrict__ field,    // (BATCH,1,64,64,64)
                     const float* __restrict__ q,        // (NQ,)
                     const float* __restrict__ xq,       // (NQ,3)
                     const int*   __restrict__ xi,
                     const int*   __restrict__ yi,
                     const int*   __restrict__ zi,
                     const float* __restrict__ normals,  // (NB,3)
                     int nb,
                     float* __restrict__ out)
{
    __shared__ float4 sq[NQ];   // {xq.x, xq.y, xq.z, q}

    const float  EPSF   = 1.1920929e-07f;               // np.finfo(float32).eps
    const float  INV4PI = 1.0f / (4.0f * 3.14159265358979323846f);
    const double DXD    = 1.0 / 63.0;                   // reference DX (float64)
    const float  RDX    = 63.0f;                        // 1/DX in fp32

    const int tid  = threadIdx.x;
    const int gtid = blockIdx.x * TPB + tid;
    const int i    = gtid >> 3;        // boundary point index
    const int c    = gtid & (CH - 1);  // charge-chunk index within point
    const bool leader = (c == 0) && (i < nb);

    // ---- Issue index loads immediately (start the memory round-trip early)
    int x = 0, y = 0, z = 0;
    if (i < nb) { x = xi[i]; y = yi[i]; z = zi[i]; }

    // ---- Stage charges into shared (one per thread, 200 <= 256)
    if (tid < NQ) {
        sq[tid] = make_float4(xq[3 * tid + 0], xq[3 * tid + 1],
                              xq[3 * tid + 2], q[tid]);
    }

    const int flat = (x * NN + y) * NN + z;

    // ---- Hoisted leader loads: normals + field stencil (both batches)
    float nx = 0.f, ny = 0.f, nz = 0.f;
    float c0[BATCH], lft[BATCH], rgt[BATCH], bel[BATCH], abv[BATCH], bck[BATCH], frt[BATCH];
    if (leader) {
        nx = normals[3 * i + 0];
        ny = normals[3 * i + 1];
        nz = normals[3 * i + 2];
        #pragma unroll
        for (int b = 0; b < BATCH; b++) {
            const float* __restrict__ o = field + b * GRID_N;
            c0[b]  = o[flat];
            lft[b] = o[flat - NN * NN];
            rgt[b] = o[flat + NN * NN];
            bel[b] = o[flat - NN];
            abv[b] = o[flat + NN];
            bck[b] = o[flat - 1];
            frt[b] = o[flat + 1];
        }
    } else {
        #pragma unroll
        for (int b = 0; b < BATCH; b++) {
            c0[b] = lft[b] = rgt[b] = bel[b] = abv[b] = bck[b] = frt[b] = 0.f;
        }
    }

    // ---- Grid-point coords: bit-exact replica of reference's fp64->fp32 points
    const float px = (float)((double)x * DXD);
    const float py = (float)((double)y * DXD);
    const float pz = (float)((double)z * DXD);

    __syncthreads();   // sq ready

    // ---- Green's function partial sums over this thread's 25 charges
    float g = 0.0f, gx = 0.0f, gy = 0.0f, gz = 0.0f;
    if (i < nb) {
        const int k0 = c * QPT;
        #pragma unroll
        for (int kk = 0; kk < QPT; kk++) {
            const float4 ch = sq[k0 + kk];
            const float dx = px - ch.x;
            const float dy = py - ch.y;
            const float dz = pz - ch.z;
            const float r2 = fmaf(dx, dx, fmaf(dy, dy, dz * dz));
            const float inv_r  = (r2 > 0.0f) ? rsqrtf(r2) : (1.0f / EPSF);
            g = fmaf(ch.w, inv_r, g);
            const float inv_r3 = inv_r * inv_r * inv_r;
            const float coef   = -ch.w * inv_r3;
            gx = fmaf(coef, dx, gx);
            gy = fmaf(coef, dy, gy);
            gz = fmaf(coef, dz, gz);
        }
    }

    // ---- Reduce 4 accumulators across the 8-thread group
    #pragma unroll
    for (int off = CH / 2; off > 0; off >>= 1) {
        g  += __shfl_down_sync(0xffffffffu, g,  off, CH);
        gx += __shfl_down_sync(0xffffffffu, gx, off, CH);
        gy += __shfl_down_sync(0xffffffffu, gy, off, CH);
        gz += __shfl_down_sync(0xffffffffu, gz, off, CH);
    }

    float local = 0.0f;
    if (leader) {
        g  *= INV4PI;
        gx *= INV4PI;
        gy *= INV4PI;
        gz *= INV4PI;

        const float gcnd = gx * nx + gy * ny + gz * nz;

        // loss1: (mol_b - out_b)^2 == g^2, identical for both batches
        local = (float)BATCH * (g * g);

        // loss2: one-sided normal derivatives per batch (preloaded stencil)
        #pragma unroll
        for (int b = 0; b < BATCH; b++) {
            const float dmx = (c0[b]  - lft[b]) * RDX;
            const float dpx = (rgt[b] - c0[b])  * RDX;
            const float dmy = (c0[b]  - bel[b]) * RDX;
            const float dpy = (abv[b] - c0[b])  * RDX;
            const float dmz = (c0[b]  - bck[b]) * RDX;
            const float dpz = (frt[b] - c0[b])  * RDX;

            const float gx_in  = (nx > 0.0f) ? dmx : dpx;
            const float gx_out = (nx > 0.0f) ? dpx : dmx;
            const float gy_in  = (ny > 0.0f) ? dmy : dpy;
            const float gy_out = (ny > 0.0f) ? dpy : dmy;
            const float gz_in  = (nz > 0.0f) ? dmz : dpz;
            const float gz_out = (nz > 0.0f) ? dpz : dmz;

            const float nd_in  = gx_in  * nx + gy_in  * ny + gz_in  * nz;
            const float nd_out = gx_out * nx + gy_out * ny + gz_out * nz;

            // E_IN = 1, E_OUT = 80
            const float t = (nd_in + gcnd) - 80.0f * nd_out;
            local = fmaf(t, t, local);
        }
    }

    // ---- Block reduction
    float v = local;
    #pragma unroll
    for (int off = 16; off > 0; off >>= 1)
        v += __shfl_down_sync(0xffffffffu, v, off);

    __shared__ float wsum[TPB / 32];
    const int warp = tid >> 5;
    const int lane = tid & 31;
    if (lane == 0) wsum[warp] = v;
    __syncthreads();

    if (warp == 0) {
        v = (lane < (TPB / 32)) ? wsum[lane] : 0.0f;
        #pragma unroll
        for (int off = (TPB / 64); off > 0; off >>= 1)
            v += __shfl_down_sync(0xffffffffu, v, off);
    }

    // ---- Cross-block tail: NO returning atomics on the critical path.
    //      Non-reducer blocks: plain STG partial -> fence -> RED.ADD (no return).
    //      Block 0: spin on the single counter word, then gather + write out.
    const unsigned int nothers = gridDim.x - 1;

    if (blockIdx.x != 0) {
        if (tid == 0) {
            g_partials[blockIdx.x] = v;        // distinct address, parallel
            __threadfence();                   // release: partial before count
            atomicAdd((unsigned int*)&g_count, 1u);   // return unused -> RED.ADD
        }
        return;
    }

    // Block 0: warp 0 holds this block's full partial in v (lane 0)
    if (warp == 0) {
        // All lanes spin on the same word (broadcast load), politely
        while (g_count != nothers) {
            __nanosleep(64);
        }
        __threadfence();                       // acquire: see all partials

        const volatile float* vp = g_partials;
        float s = (lane == 0) ? v : 0.0f;      // own partial
        for (unsigned int j = 1 + lane; j <= nothers; j += 32)
            s += vp[j];
        #pragma unroll
        for (int off = 16; off > 0; off >>= 1)
            s += __shfl_down_sync(0xffffffffu, s, off);

        if (lane == 0) {
            out[0] = s * (1.0f / (float)(BATCH * nb));
            g_count = 0;                       // reset for next graph replay
            __threadfence();
        }
    }
}

extern "C" void kernel_launch(void* const* d_in, const int* in_sizes, int n_in,
                              void* d_out, int out_size)
{
    const float* field   = (const float*)d_in[0];  // output (2,1,64,64,64)
    const float* q       = (const float*)d_in[1];  // (200,)
    const float* xq      = (const float*)d_in[2];  // (200,3)
    // d_in[3] = points (recomputed on device bit-exactly)
    const int*   xi      = (const int*)  d_in[4];
    const int*   yi      = (const int*)  d_in[5];
    const int*   zi      = (const int*)  d_in[6];
    const float* normals = (const float*)d_in[7];  // (NB,3)
    float*       out     = (float*)d_out;

    const int nb = in_sizes[4];

    int blocks = (nb + PPB - 1) / PPB;   // ~147 for nb ~ 4.7K
    if (blocks > MAXB) blocks = MAXB;

    ibl_loss_kernel<<<blocks, TPB>>>(field, q, xq, xi, yi, zi, normals, nb, out);
}

// round 14
// speedup vs baseline: 1.2316x; 1.0294x over previous
#include <cuda_runtime.h>
#include <math.h>

// Problem constants (fixed by the reference)
#define NN      64
#define GRID_N  (NN * NN * NN)   // 262144
#define NQ      200
#define BATCH   2
#define CH      8                // threads cooperating per boundary point
#define QPT     (NQ / CH)        // 25 charges per thread
#define TPB     256
#define PPB     (TPB / CH)       // 32 boundary points per block
#define MAXB    2048

// Cross-block reduction scratch (allocation-free __device__ globals).
// Every live slot is overwritten every launch; ticket wraps -> replay-safe.
__device__ float        g_partials[MAXB];
__device__ unsigned int g_ticket = 0;   // self-resetting via atomicInc wrap

__global__ __launch_bounds__(TPB)
void ibl_loss_kernel(const float* __restrict__ field,    // (BATCH,1,64,64,64)
                     const float* __restrict__ q,        // (NQ,)
                     const float* __restrict__ xq,       // (NQ,3)
                     const int*   __restrict__ xi,
                     const int*   __restrict__ yi,
                     const int*   __restrict__ zi,
                     const float* __restrict__ normals,  // (NB,3)
                     int nb,
                     float* __restrict__ out)
{
    __shared__ float4 sq[NQ];   // {xq.x, xq.y, xq.z, q}

    const float  EPSF   = 1.1920929e-07f;               // np.finfo(float32).eps
    const float  INV4PI = 1.0f / (4.0f * 3.14159265358979323846f);
    const double DXD    = 1.0 / 63.0;                   // reference DX (float64)
    const float  RDX    = 63.0f;                        // 1/DX in fp32

    const int tid  = threadIdx.x;
    const int gtid = blockIdx.x * TPB + tid;
    const int i    = gtid >> 3;        // boundary point index
    const int c    = gtid & (CH - 1);  // charge-chunk index within point
    const bool leader = (c == 0) && (i < nb);

    // ---- Issue index loads immediately (start the memory round-trip early)
    int x = 0, y = 0, z = 0;
    if (i < nb) { x = xi[i]; y = yi[i]; z = zi[i]; }

    // ---- Stage charges into shared (one per thread, 200 <= 256)
    if (tid < NQ) {
        sq[tid] = make_float4(xq[3 * tid + 0], xq[3 * tid + 1],
                              xq[3 * tid + 2], q[tid]);
    }

    const int flat = (x * NN + y) * NN + z;

    // ---- Hoisted leader loads: normals + field stencil (both batches);
    //      their latency overlaps staging + the charge loop.
    float nx = 0.f, ny = 0.f, nz = 0.f;
    float c0[BATCH], lft[BATCH], rgt[BATCH], bel[BATCH], abv[BATCH], bck[BATCH], frt[BATCH];
    if (leader) {
        nx = normals[3 * i + 0];
        ny = normals[3 * i + 1];
        nz = normals[3 * i + 2];
        #pragma unroll
        for (int b = 0; b < BATCH; b++) {
            const float* __restrict__ o = field + b * GRID_N;
            c0[b]  = o[flat];
            lft[b] = o[flat - NN * NN];
            rgt[b] = o[flat + NN * NN];
            bel[b] = o[flat - NN];
            abv[b] = o[flat + NN];
            bck[b] = o[flat - 1];
            frt[b] = o[flat + 1];
        }
    } else {
        #pragma unroll
        for (int b = 0; b < BATCH; b++) {
            c0[b] = lft[b] = rgt[b] = bel[b] = abv[b] = bck[b] = frt[b] = 0.f;
        }
    }

    // ---- Grid-point coords: bit-exact replica of reference's fp64->fp32 points
    //      (removes the dependent points[flat] DRAM gather entirely)
    const float px = (float)((double)x * DXD);
    const float py = (float)((double)y * DXD);
    const float pz = (float)((double)z * DXD);

    __syncthreads();   // sq ready

    // ---- Green's function partial sums over this thread's 25 charges
    float g = 0.0f, gx = 0.0f, gy = 0.0f, gz = 0.0f;
    if (i < nb) {
        const int k0 = c * QPT;
        #pragma unroll
        for (int kk = 0; kk < QPT; kk++) {
            const float4 ch = sq[k0 + kk];
            const float dx = px - ch.x;
            const float dy = py - ch.y;
            const float dz = pz - ch.z;
            const float r2 = fmaf(dx, dx, fmaf(dy, dy, dz * dz));
            const float inv_r  = (r2 > 0.0f) ? rsqrtf(r2) : (1.0f / EPSF);
            g = fmaf(ch.w, inv_r, g);
            const float inv_r3 = inv_r * inv_r * inv_r;
            const float coef   = -ch.w * inv_r3;
            gx = fmaf(coef, dx, gx);
            gy = fmaf(coef, dy, gy);
            gz = fmaf(coef, dz, gz);
        }
    }

    // ---- Reduce 4 accumulators across the 8-thread group
    #pragma unroll
    for (int off = CH / 2; off > 0; off >>= 1) {
        g  += __shfl_down_sync(0xffffffffu, g,  off, CH);
        gx += __shfl_down_sync(0xffffffffu, gx, off, CH);
        gy += __shfl_down_sync(0xffffffffu, gy, off, CH);
        gz += __shfl_down_sync(0xffffffffu, gz, off, CH);
    }

    float local = 0.0f;
    if (leader) {
        g  *= INV4PI;
        gx *= INV4PI;
        gy *= INV4PI;
        gz *= INV4PI;

        const float gcnd = gx * nx + gy * ny + gz * nz;

        // loss1: (mol_b - out_b)^2 == g^2, identical for both batches
        local = (float)BATCH * (g * g);

        // loss2: one-sided normal derivatives per batch (preloaded stencil)
        #pragma unroll
        for (int b = 0; b < BATCH; b++) {
            const float dmx = (c0[b]  - lft[b]) * RDX;
            const float dpx = (rgt[b] - c0[b])  * RDX;
            const float dmy = (c0[b]  - bel[b]) * RDX;
            const float dpy = (abv[b] - c0[b])  * RDX;
            const float dmz = (c0[b]  - bck[b]) * RDX;
            const float dpz = (frt[b] - c0[b])  * RDX;

            const float gx_in  = (nx > 0.0f) ? dmx : dpx;
            const float gx_out = (nx > 0.0f) ? dpx : dmx;
            const float gy_in  = (ny > 0.0f) ? dmy : dpy;
            const float gy_out = (ny > 0.0f) ? dpy : dmy;
            const float gz_in  = (nz > 0.0f) ? dmz : dpz;
            const float gz_out = (nz > 0.0f) ? dpz : dmz;

            const float nd_in  = gx_in  * nx + gy_in  * ny + gz_in  * nz;
            const float nd_out = gx_out * nx + gy_out * ny + gz_out * nz;

            // E_IN = 1, E_OUT = 80
            const float t = (nd_in + gcnd) - 80.0f * nd_out;
            local = fmaf(t, t, local);
        }
    }

    // ---- Block reduction. Non-zero `local` sits only at lanes 0,8,16,24:
    //      two shuffles (16, 8) fold them into lane 0 of each warp.
    float v = local;
    v += __shfl_down_sync(0xffffffffu, v, 16);
    v += __shfl_down_sync(0xffffffffu, v, 8);

    __shared__ float wsum[TPB / 32];
    const int warp = tid >> 5;
    const int lane = tid & 31;
    if (lane == 0) wsum[warp] = v;
    __syncthreads();

    if (warp == 0) {
        v = (lane < (TPB / 32)) ? wsum[lane] : 0.0f;
        #pragma unroll
        for (int off = (TPB / 64); off > 0; off >>= 1)
            v += __shfl_down_sync(0xffffffffu, v, off);
    }

    // ---- Cross-block tail (R4-proven): STG partial -> fence -> ticket;
    //      last-arriving block gathers the partials and writes the scalar.
    const int nblocks = gridDim.x;
    __shared__ bool s_is_last;
    if (tid == 0) {
        g_partials[blockIdx.x] = v;
        __threadfence();
        unsigned int t = atomicInc(&g_ticket, (unsigned int)(nblocks - 1));
        s_is_last = (t == (unsigned int)(nblocks - 1));
    }
    __syncthreads();

    if (s_is_last && warp == 0) {
        const volatile float* vp = g_partials;   // post-fence L2 reads
        float s = 0.0f;
        for (int j = lane; j < nblocks; j += 32)
            s += vp[j];
        #pragma unroll
        for (int off = 16; off > 0; off >>= 1)
            s += __shfl_down_sync(0xffffffffu, s, off);
        if (lane == 0) {
            out[0] = s * (1.0f / (float)(BATCH * nb));
        }
    }
}

extern "C" void kernel_launch(void* const* d_in, const int* in_sizes, int n_in,
                              void* d_out, int out_size)
{
    const float* field   = (const float*)d_in[0];  // output (2,1,64,64,64)
    const float* q       = (const float*)d_in[1];  // (200,)
    const float* xq      = (const float*)d_in[2];  // (200,3)
    // d_in[3] = points (recomputed on device bit-exactly)
    const int*   xi      = (const int*)  d_in[4];
    const int*   yi      = (const int*)  d_in[5];
    const int*   zi      = (const int*)  d_in[6];
    const float* normals = (const float*)d_in[7];  // (NB,3)
    float*       out     = (float*)d_out;

    const int nb = in_sizes[4];

    int blocks = (nb + PPB - 1) / PPB;   // ~147 for nb ~ 4.7K
    if (blocks > MAXB) blocks = MAXB;

    ibl_loss_kernel<<<blocks, TPB>>>(field, q, xq, xi, yi, zi, normals, nb, out);
}